// round 11
// baseline (speedup 1.0000x reference)
#include <cuda_runtime.h>

// Problem constants
#define T_STEPS 168
#define IN_DIM  16
#define NH1     64
#define NH2     32
#define NG1     256   // 4*H1
#define NG2     128   // 4*H2
#define BATCH   4096

// Tiling: one wave — 147 CTAs on 148 SMs, 512 threads each
#define NB   28
#define BLK  512
#define GRID ((BATCH + NB - 1) / NB)   // 147

// Strides (floats): ≡ 0 mod 4 (float4 align), ≡ 4 mod 8 → conflict-free
// lane-strided LDS.128 (stride/4 odd → 8-lane phases hit distinct banks)
#define W1_STRIDE  84    // 16 (x) + 64 (h1) + 4 pad
#define W2_STRIDE  100   // 64 (h1) + 32 (h2) + 4 pad
#define IN1_STRIDE 84    // [0:16]=x  [16:80]=h1
#define H2_STRIDE  36    // [0:32]=h2 + 4 pad

#define IN1_BUF (NB * IN1_STRIDE)    // 2352
#define H2_BUF  (NB * H2_STRIDE)     // 1008

#define OFF_W1   0
#define OFF_W2   (OFF_W1  + NG1 * W1_STRIDE)     // 21504
#define OFF_B1   (OFF_W2  + NG2 * W2_STRIDE)     // 34304
#define OFF_B2   (OFF_B1  + NG1)                 // 34560
#define OFF_WFC  (OFF_B2  + NG2)                 // 34688
#define OFF_IN1  (OFF_WFC + 32)                  // 34720  double buffer [2][28][84]
#define OFF_H2   (OFF_IN1 + 2 * IN1_BUF)         // 39424  double buffer [2][28][36]
#define SMEM_FLOATS (OFF_H2 + 2 * H2_BUF)        // 41440 floats ≈ 166 KB

typedef unsigned long long u64;

__device__ __forceinline__ void fma2(u64& d, u64 a, u64 b) {
    asm("fma.rn.f32x2 %0, %1, %2, %0;" : "+l"(d) : "l"(a), "l"(b));
}
__device__ __forceinline__ u64 pack2(float lo, float hi) {
    u64 r; asm("mov.b64 %0, {%1, %2};" : "=l"(r) : "f"(lo), "f"(hi)); return r;
}
__device__ __forceinline__ float pairsum(u64 v) {
    float lo, hi;
    asm("mov.b64 {%0, %1}, %2;" : "=f"(lo), "=f"(hi) : "l"(v));
    return lo + hi;
}
// single-MUFU activations (MUFU.TANH)
__device__ __forceinline__ float tanh_(float v) {
    float r; asm("tanh.approx.f32 %0, %1;" : "=f"(r) : "f"(v)); return r;
}
__device__ __forceinline__ float sigm_(float v) {
    return fmaf(0.5f, tanh_(0.5f * v), 0.5f);
}

extern __shared__ float smem[];

__global__ __launch_bounds__(BLK, 1)
void lstm2_fused_kernel(const float* __restrict__ x,
                        const float* __restrict__ Wih1, const float* __restrict__ Whh1,
                        const float* __restrict__ bih1, const float* __restrict__ bhh1,
                        const float* __restrict__ Wih2, const float* __restrict__ Whh2,
                        const float* __restrict__ bih2, const float* __restrict__ bhh2,
                        const float* __restrict__ Wfc,  const float* __restrict__ bfc,
                        float* __restrict__ out)
{
    const int tid = threadIdx.x;
    const int b0  = blockIdx.x * NB;

    float* sW1  = smem + OFF_W1;
    float* sW2  = smem + OFF_W2;
    float* sB1  = smem + OFF_B1;
    float* sB2  = smem + OFF_B2;
    float* sWfc = smem + OFF_WFC;
    float* sIn1 = smem + OFF_IN1;
    float* sH2  = smem + OFF_H2;

    // ---- weights into shared (combined [x;h] rows, padded strides) ----
    for (int i = tid; i < NG1 * W1_STRIDE; i += BLK) {
        int g = i / W1_STRIDE, k = i % W1_STRIDE;
        float v = 0.f;
        if (k < IN_DIM)            v = Wih1[g * IN_DIM + k];
        else if (k < IN_DIM + NH1) v = Whh1[g * NH1 + (k - IN_DIM)];
        sW1[i] = v;
    }
    for (int i = tid; i < NG2 * W2_STRIDE; i += BLK) {
        int g = i / W2_STRIDE, k = i % W2_STRIDE;
        float v = 0.f;
        if (k < NH1)            v = Wih2[g * NH1 + k];
        else if (k < NH1 + NH2) v = Whh2[g * NH2 + (k - NH1)];
        sW2[i] = v;
    }
    if (tid < NG1) sB1[tid] = bih1[tid] + bhh1[tid];
    if (tid < NG2) sB2[tid] = bih2[tid] + bhh2[tid];
    if (tid < NH2) sWfc[tid] = Wfc[tid];
    for (int i = tid; i < 2 * IN1_BUF; i += BLK) sIn1[i] = 0.f;
    for (int i = tid; i < 2 * H2_BUF;  i += BLK) sH2[i] = 0.f;

    // ---- role split (address arithmetic only — NO smem data reads here) ----
    // warps 0-7  (tid 0..255):   L1 fused — 128 lane-pairs x 2 halves of 14 batches
    // warps 8-11 (tid 256..383): L2 fused — 64 lane-pairs x 2 halves of 14 batches
    // warps 12-15 (tid 384..511): x publish/prefetch
    const int lane = tid & 31;
    const int wid  = tid >> 5;

    // L1 mapping
    const int u1  = ((wid & 3) << 4) + (lane & 15);   // 0..63
    const int s1  = lane >> 4;                        // 0..1
    const int bh1 = (wid >> 2) & 1;                   // batch half
    const float* w1a = sW1 + (u1 + s1 * 64) * W1_STRIDE;        // i or f
    const float* w1b = sW1 + (128 + u1 + s1 * 64) * W1_STRIDE;  // g or o

    // L2 mapping (valid for wid 8..11)
    const int u2  = ((wid & 1) << 4) + (lane & 15);   // 0..31
    const int s2  = lane >> 4;
    const int bh2 = (wid >> 1) & 1;
    const float* w2a = sW2 + (u2 + s2 * 32) * W2_STRIDE;        // i or f
    const float* w2b = sW2 + (u2 + 64 + s2 * 32) * W2_STRIDE;   // g or o

    // AUX mapping: x publishers, 112 of 128 threads
    const int  xi   = tid - 384;
    const bool xact = (tid >= 384) && (xi < NB * (IN_DIM / 4));  // 112
    const int  xb   = xi >> 2;
    const int  xk4  = xi & 3;
    const bool xval = xact && (b0 + xb) < BATCH;
    const float* xptr = xval ? (x + ((long)(b0 + xb) * T_STEPS) * IN_DIM + xk4 * 4)
                             : x;
    float4 xreg = make_float4(0.f, 0.f, 0.f, 0.f);
    if (xval) xreg = *(const float4*)xptr;

    __syncthreads();
    if (xact) *(float4*)&sIn1[xb * IN1_STRIDE + xk4 * 4] = xreg;   // x(0) -> buf0
    if (xval) xreg = *(const float4*)(xptr + IN_DIM);              // x(1)
    __syncthreads();

    // ---- bias reads — AFTER the barrier so all init writes are visible ----
    const float bb1a = sB1[u1 + s1 * 64];
    const float bb1b = sB1[128 + u1 + s1 * 64];
    const float bb2a = sB2[u2 + s2 * 32];
    const float bb2b = sB2[u2 + 64 + s2 * 32];

    float c1r[14], c2r[14];
#pragma unroll
    for (int j = 0; j < 14; j++) { c1r[j] = 0.f; c2r[j] = 0.f; }

    for (int t = 0; t <= T_STEPS; t++) {
        const float* rb = sIn1 + (t & 1) * IN1_BUF;        // x(t), h1(t-1)
        float*       wb = sIn1 + ((t + 1) & 1) * IN1_BUF;  // x(t+1), h1(t)

        if (tid < 256) {
            // ---- L1: gates(t) + cell(t), 2 gates x 14 batches ----
            if (t < T_STEPS) {
                u64 acca[14], accb[14];
#pragma unroll
                for (int b = 0; b < 14; b++) {
                    acca[b] = pack2(bb1a, 0.f);
                    accb[b] = pack2(bb1b, 0.f);
                }
                const float* in1q = rb + (bh1 * 14) * IN1_STRIDE;
#pragma unroll 4
                for (int k4 = 0; k4 < (IN_DIM + NH1) / 4; k4++) {      // 20
                    const ulonglong2 wa = *(const ulonglong2*)(w1a + k4 * 4);
                    const ulonglong2 wbv = *(const ulonglong2*)(w1b + k4 * 4);
#pragma unroll
                    for (int b = 0; b < 14; b++) {
                        const ulonglong2 h =
                            *(const ulonglong2*)(in1q + b * IN1_STRIDE + k4 * 4);
                        fma2(acca[b], wa.x, h.x);
                        fma2(acca[b], wa.y, h.y);
                        fma2(accb[b], wbv.x, h.x);
                        fma2(accb[b], wbv.y, h.y);
                    }
                }
                // epilogue: exchange i,f,g,o across xor-16 lanes; update c1; write h1(t)
#pragma unroll
                for (int j = 0; j < 14; j++) {
                    const float vA = sigm_(pairsum(acca[j]));             // i or f
                    const float vBr = pairsum(accb[j]);
                    const float vB = (s1 == 0) ? tanh_(vBr) : sigm_(vBr); // g or o
                    const float pA = __shfl_xor_sync(0xffffffffu, vA, 16);
                    const float pB = __shfl_xor_sync(0xffffffffu, vB, 16);
                    const float i_ = (s1 == 0) ? vA : pA;
                    const float f_ = (s1 == 0) ? pA : vA;
                    const float g_ = (s1 == 0) ? vB : pB;
                    const float o_ = (s1 == 0) ? pB : vB;
                    c1r[j] = fmaf(f_, c1r[j], i_ * g_);
                    const float h = o_ * tanh_(c1r[j]);
                    if ((j & 1) == s1)
                        wb[(bh1 * 14 + j) * IN1_STRIDE + IN_DIM + u1] = h;
                }
            }
        } else if (tid < 384) {
            // ---- L2: gates(t-1) + cell(t-1), 2 gates x 14 batches ----
            if (t >= 1) {
                u64 acca[14], accb[14];
#pragma unroll
                for (int b = 0; b < 14; b++) {
                    acca[b] = pack2(bb2a, 0.f);
                    accb[b] = pack2(bb2b, 0.f);
                }
                const float* h1q = rb + (bh2 * 14) * IN1_STRIDE + IN_DIM;        // h1(t-1)
                const float* h2q = sH2 + (t & 1) * H2_BUF + (bh2 * 14) * H2_STRIDE; // h2(t-2)
#pragma unroll 4
                for (int k4 = 0; k4 < NH1 / 4; k4++) {                  // 16
                    const ulonglong2 wa = *(const ulonglong2*)(w2a + k4 * 4);
                    const ulonglong2 wbv = *(const ulonglong2*)(w2b + k4 * 4);
#pragma unroll
                    for (int b = 0; b < 14; b++) {
                        const ulonglong2 h =
                            *(const ulonglong2*)(h1q + b * IN1_STRIDE + k4 * 4);
                        fma2(acca[b], wa.x, h.x);
                        fma2(acca[b], wa.y, h.y);
                        fma2(accb[b], wbv.x, h.x);
                        fma2(accb[b], wbv.y, h.y);
                    }
                }
#pragma unroll 4
                for (int k4 = 0; k4 < NH2 / 4; k4++) {                  // 8
                    const ulonglong2 wa = *(const ulonglong2*)(w2a + NH1 + k4 * 4);
                    const ulonglong2 wbv = *(const ulonglong2*)(w2b + NH1 + k4 * 4);
#pragma unroll
                    for (int b = 0; b < 14; b++) {
                        const ulonglong2 h =
                            *(const ulonglong2*)(h2q + b * H2_STRIDE + k4 * 4);
                        fma2(acca[b], wa.x, h.x);
                        fma2(acca[b], wa.y, h.y);
                        fma2(accb[b], wbv.x, h.x);
                        fma2(accb[b], wbv.y, h.y);
                    }
                }
                float* h2w = sH2 + ((t + 1) & 1) * H2_BUF + (bh2 * 14) * H2_STRIDE; // h2(t-1)
#pragma unroll
                for (int j = 0; j < 14; j++) {
                    const float vA = sigm_(pairsum(acca[j]));             // i or f
                    const float vBr = pairsum(accb[j]);
                    const float vB = (s2 == 0) ? tanh_(vBr) : sigm_(vBr); // g or o
                    const float pA = __shfl_xor_sync(0xffffffffu, vA, 16);
                    const float pB = __shfl_xor_sync(0xffffffffu, vB, 16);
                    const float i_ = (s2 == 0) ? vA : pA;
                    const float f_ = (s2 == 0) ? pA : vA;
                    const float g_ = (s2 == 0) ? vB : pB;
                    const float o_ = (s2 == 0) ? pB : vB;
                    c2r[j] = fmaf(f_, c2r[j], i_ * g_);
                    const float h = o_ * tanh_(c2r[j]);
                    if ((j & 1) == s2)
                        h2w[j * H2_STRIDE + u2] = h;
                }
            }
        } else {
            // ---- AUX: publish x(t+1) into write buffer; prefetch x(t+2) ----
            if (t < T_STEPS) {
                if (xact && (t + 1) < T_STEPS)
                    *(float4*)&wb[xb * IN1_STRIDE + xk4 * 4] = xreg;
                if (xval && (t + 2) < T_STEPS)
                    xreg = *(const float4*)(xptr + (long)(t + 2) * IN_DIM);
            }
        }

        __syncthreads();                 // single per-step barrier
    }

    // ---- final FC: out[b] = h2(T-1) . Wfc + bfc ----
    // h2(T-1) was written at iteration t=T into buffer ((T+1)&1)
    if (tid < NB) {
        const int bg = b0 + tid;
        if (bg < BATCH) {
            const float* h2f = sH2 + ((T_STEPS + 1) & 1) * H2_BUF
                                   + tid * H2_STRIDE;
            float s = bfc[0];
#pragma unroll
            for (int u = 0; u < NH2; u++)
                s = fmaf(h2f[u], sWfc[u], s);
            out[bg] = s;
        }
    }
}

extern "C" void kernel_launch(void* const* d_in, const int* in_sizes, int n_in,
                              void* d_out, int out_size)
{
    const float* x    = (const float*)d_in[0];
    const float* Wih1 = (const float*)d_in[1];
    const float* Whh1 = (const float*)d_in[2];
    const float* bih1 = (const float*)d_in[3];
    const float* bhh1 = (const float*)d_in[4];
    const float* Wih2 = (const float*)d_in[5];
    const float* Whh2 = (const float*)d_in[6];
    const float* bih2 = (const float*)d_in[7];
    const float* bhh2 = (const float*)d_in[8];
    const float* Wfc  = (const float*)d_in[9];
    const float* bfc  = (const float*)d_in[10];
    float* out = (float*)d_out;

    const size_t smem_bytes = SMEM_FLOATS * sizeof(float);  // ~166 KB
    cudaFuncSetAttribute(lstm2_fused_kernel,
                         cudaFuncAttributeMaxDynamicSharedMemorySize,
                         (int)smem_bytes);

    lstm2_fused_kernel<<<GRID, BLK, smem_bytes>>>(
        x, Wih1, Whh1, bih1, bhh1, Wih2, Whh2, bih2, bhh2, Wfc, bfc, out);
}

// round 12
// speedup vs baseline: 1.1783x; 1.1783x over previous
#include <cuda_runtime.h>

// Problem constants
#define T_STEPS 168
#define IN_DIM  16
#define NH1     64
#define NH2     32
#define NG1     256   // 4*H1
#define NG2     128   // 4*H2
#define BATCH   4096

// Tiling: one wave — 147 CTAs on 148 SMs, 512 threads each
#define NB   28
#define BLK  512
#define GRID ((BATCH + NB - 1) / NB)   // 147

// Strides (floats): ≡ 0 mod 4 (float4 align), ≡ 4 mod 8 → conflict-free
// lane-strided LDS.128
#define W1_STRIDE  84    // 16 (x) + 64 (h1) + 4 pad
#define W2_STRIDE  100   // 64 (h1) + 32 (h2) + 4 pad
#define IN1_STRIDE 84    // [0:16]=x  [16:80]=h1
#define IN2_STRIDE 68    // [0:64]=h1 + 4 pad
#define H2_STRIDE  36    // [0:32]=h2 + 4 pad

#define H2_BUF  (NB * H2_STRIDE)     // 1008

#define OFF_W1   0
#define OFF_W2   (OFF_W1  + NG1 * W1_STRIDE)
#define OFF_B1   (OFF_W2  + NG2 * W2_STRIDE)
#define OFF_B2   (OFF_B1  + NG1)
#define OFF_WFC  (OFF_B2  + NG2)
#define OFF_IN1  (OFF_WFC + 32)
#define OFF_IN2  (OFF_IN1 + NB * IN1_STRIDE)
#define OFF_H2   (OFF_IN2 + NB * IN2_STRIDE)     // double buffer [2][28][36]
#define OFF_G1   (OFF_H2  + 2 * H2_BUF)
#define OFF_PART (OFF_G1  + NB * NG1)            // partials [14][256] u64
#define SMEM_FLOATS (OFF_PART + 14 * 256 * 2)    // 54208 floats ≈ 217 KB

typedef unsigned long long u64;

__device__ __forceinline__ void fma2(u64& d, u64 a, u64 b) {
    asm("fma.rn.f32x2 %0, %1, %2, %0;" : "+l"(d) : "l"(a), "l"(b));
}
__device__ __forceinline__ u64 pack2(float lo, float hi) {
    u64 r; asm("mov.b64 %0, {%1, %2};" : "=l"(r) : "f"(lo), "f"(hi)); return r;
}
__device__ __forceinline__ float pairsum(u64 v) {
    float lo, hi;
    asm("mov.b64 {%0, %1}, %2;" : "=f"(lo), "=f"(hi) : "l"(v));
    return lo + hi;
}
// single-MUFU activations (MUFU.TANH)
__device__ __forceinline__ float tanh_(float v) {
    float r; asm("tanh.approx.f32 %0, %1;" : "=f"(r) : "f"(v)); return r;
}
__device__ __forceinline__ float sigm_(float v) {
    return fmaf(0.5f, tanh_(0.5f * v), 0.5f);
}

extern __shared__ float smem[];

__global__ __launch_bounds__(BLK, 1)
void lstm2_fused_kernel(const float* __restrict__ x,
                        const float* __restrict__ Wih1, const float* __restrict__ Whh1,
                        const float* __restrict__ bih1, const float* __restrict__ bhh1,
                        const float* __restrict__ Wih2, const float* __restrict__ Whh2,
                        const float* __restrict__ bih2, const float* __restrict__ bhh2,
                        const float* __restrict__ Wfc,  const float* __restrict__ bfc,
                        float* __restrict__ out)
{
    const int tid = threadIdx.x;
    const int b0  = blockIdx.x * NB;

    float* sW1   = smem + OFF_W1;
    float* sW2   = smem + OFF_W2;
    float* sB1   = smem + OFF_B1;
    float* sB2   = smem + OFF_B2;
    float* sWfc  = smem + OFF_WFC;
    float* sIn1  = smem + OFF_IN1;
    float* sIn2  = smem + OFF_IN2;
    float* sH2   = smem + OFF_H2;
    float* sG1   = smem + OFF_G1;
    float* sPart = smem + OFF_PART;

    // ---- weights into shared (combined [x;h] rows, padded strides) ----
    for (int i = tid; i < NG1 * W1_STRIDE; i += BLK) {
        int g = i / W1_STRIDE, k = i % W1_STRIDE;
        float v = 0.f;
        if (k < IN_DIM)            v = Wih1[g * IN_DIM + k];
        else if (k < IN_DIM + NH1) v = Whh1[g * NH1 + (k - IN_DIM)];
        sW1[i] = v;
    }
    for (int i = tid; i < NG2 * W2_STRIDE; i += BLK) {
        int g = i / W2_STRIDE, k = i % W2_STRIDE;
        float v = 0.f;
        if (k < NH1)            v = Wih2[g * NH1 + k];
        else if (k < NH1 + NH2) v = Whh2[g * NH2 + (k - NH1)];
        sW2[i] = v;
    }
    if (tid < NG1) sB1[tid] = bih1[tid] + bhh1[tid];
    if (tid < NG2) sB2[tid] = bih2[tid] + bhh2[tid];
    if (tid < NH2) sWfc[tid] = Wfc[tid];
    for (int i = tid; i < NB * IN1_STRIDE; i += BLK) sIn1[i] = 0.f;
    for (int i = tid; i < NB * IN2_STRIDE; i += BLK) sIn2[i] = 0.f;
    for (int i = tid; i < 2 * H2_BUF;  i += BLK) sH2[i] = 0.f;

    // ---- x prefetch: 112 threads each own one float4 (b, k4) ----
    const bool xact = (tid < NB * (IN_DIM / 4));          // 112
    const int  xb   = tid >> 2;
    const int  xk4  = tid & 3;
    const bool xval = xact && (b0 + xb) < BATCH;
    const float* xptr = x + ((long)(b0 + xb) * T_STEPS) * IN_DIM + xk4 * 4;
    float4 xreg = make_float4(0.f, 0.f, 0.f, 0.f);
    if (xval) xreg = *(const float4*)xptr;

    __syncthreads();
    if (xact) *(float4*)&sIn1[xb * IN1_STRIDE + xk4 * 4] = xreg;   // x(0)
    if (xval) xreg = *(const float4*)(xptr + IN_DIM);              // x(1)
    __syncthreads();

    // ---- phase 2 mapping: 128 gate-pairs (p, p+128) x 4 batch-quarters of 7 ----
    const int p   = tid & 127;
    const int q2  = tid >> 7;           // 0..3
    const float* w1a = sW1 + p * W1_STRIDE;
    const float* w1b = sW1 + (p + 128) * W1_STRIDE;
    const float  bb1a = sB1[p];
    const float  bb1b = sB1[p + 128];
    const bool   b_is_tanh = (p < 64);  // gate p+128 is 'g' iff p<64

    // ---- phase 3 mapping: 448 threads = 64 units x 7 batch-groups of 4 ----
    const int u3  = tid & 63;
    const int bq3 = tid >> 6;           // 0..7, group 7 idle
    float c1r[4];
#pragma unroll
    for (int j = 0; j < 4; j++) c1r[j] = 0.f;

    // ---- phase 4+5 split-K mapping: both 256-thread halves own the SAME
    // slot grid (uf, sf, qf) computed from tid&255; consumers (tid<256)
    // do h1 k4 0..11 + bias; producers (tid>=256) do h1 k4 12..15 + h2 k4 0..7
    // and export partial accumulators through sPart.
    const int t2 = tid & 255;
    const int uf = ((t2 >> 5) & 1) * 16 + (t2 & 15);   // 0..31
    const int sf = (t2 >> 4) & 1;
    const int qf = t2 >> 6;                            // 0..3
    const float* wA = sW2 + (uf + sf * 32) * W2_STRIDE;        // i or f
    const float* wB = sW2 + (uf + 64 + sf * 32) * W2_STRIDE;   // g or o
    const float  bbA = sB2[uf + sf * 32];
    const float  bbB = sB2[uf + 64 + sf * 32];
    float c2r[7];
#pragma unroll
    for (int j = 0; j < 7; j++) c2r[j] = 0.f;

    for (int t = 0; t < T_STEPS; t++) {
        // ---- phase 2: layer-1 gates (2 gates x 7 batches per thread) ----
        {
            u64 acca[7], accb[7];
#pragma unroll
            for (int b = 0; b < 7; b++) {
                acca[b] = pack2(bb1a, 0.f);
                accb[b] = pack2(bb1b, 0.f);
            }
            const float* in1q = sIn1 + (q2 * 7) * IN1_STRIDE;
#pragma unroll 4
            for (int k4 = 0; k4 < (IN_DIM + NH1) / 4; k4++) {      // 20
                const ulonglong2 wa = *(const ulonglong2*)(w1a + k4 * 4);
                const ulonglong2 wb = *(const ulonglong2*)(w1b + k4 * 4);
#pragma unroll
                for (int b = 0; b < 7; b++) {
                    const ulonglong2 h = *(const ulonglong2*)(in1q + b * IN1_STRIDE + k4 * 4);
                    fma2(acca[b], wa.x, h.x);
                    fma2(acca[b], wa.y, h.y);
                    fma2(accb[b], wb.x, h.x);
                    fma2(accb[b], wb.y, h.y);
                }
            }
#pragma unroll
            for (int b = 0; b < 7; b++) {
                const int bb = q2 * 7 + b;
                sG1[bb * NG1 + p]       = sigm_(pairsum(acca[b]));
                const float vb = pairsum(accb[b]);
                sG1[bb * NG1 + 128 + p] = b_is_tanh ? tanh_(vb) : sigm_(vb);
            }
        }
        __syncthreads();                              // B

        // ---- phase 3: layer-1 cell/h update (c1 in regs) + x(t+1) publish ----
        if (xact && (t + 1) < T_STEPS)
            *(float4*)&sIn1[xb * IN1_STRIDE + xk4 * 4] = xreg;
        if (xval && (t + 2) < T_STEPS)
            xreg = *(const float4*)(xptr + (long)(t + 2) * IN_DIM);

        if (bq3 < 7) {
#pragma unroll
            for (int j = 0; j < 4; j++) {
                const int b = bq3 * 4 + j;
                const float i_ = sG1[b * NG1 + u3];
                const float f_ = sG1[b * NG1 + NH1 + u3];
                const float g_ = sG1[b * NG1 + 2 * NH1 + u3];
                const float o_ = sG1[b * NG1 + 3 * NH1 + u3];
                c1r[j] = fmaf(f_, c1r[j], i_ * g_);
                const float h = o_ * tanh_(c1r[j]);
                sIn1[b * IN1_STRIDE + IN_DIM + u3] = h;
                sIn2[b * IN2_STRIDE + u3]          = h;
            }
        }
        __syncthreads();                              // C

        // ---- phase 4+5 split-K: layer-2 gates + cell update ----
        if (tid < 256) {
            // consumer: h1 k4 0..11 with bias
            u64 accA[7], accB[7];
#pragma unroll
            for (int b = 0; b < 7; b++) {
                accA[b] = pack2(bbA, 0.f);
                accB[b] = pack2(bbB, 0.f);
            }
            const float* in2q = sIn2 + (qf * 7) * IN2_STRIDE;
#pragma unroll 4
            for (int k4 = 0; k4 < 12; k4++) {
                const ulonglong2 wa = *(const ulonglong2*)(wA + k4 * 4);
                const ulonglong2 wb = *(const ulonglong2*)(wB + k4 * 4);
#pragma unroll
                for (int b = 0; b < 7; b++) {
                    const ulonglong2 h = *(const ulonglong2*)(in2q + b * IN2_STRIDE + k4 * 4);
                    fma2(accA[b], wa.x, h.x);
                    fma2(accA[b], wa.y, h.y);
                    fma2(accB[b], wb.x, h.x);
                    fma2(accB[b], wb.y, h.y);
                }
            }
            // wait for producers' partials
            asm volatile("bar.sync 3, 512;" ::: "memory");

            float* h2w = sH2 + (t & 1) * H2_BUF + (qf * 7) * H2_STRIDE;   // h2(t)
#pragma unroll
            for (int j = 0; j < 7; j++) {
                const u64 pAp = *(const u64*)&sPart[(j * 256 + t2) * 2];
                const u64 pBp = *(const u64*)&sPart[((j + 7) * 256 + t2) * 2];
                const float vA = sigm_(pairsum(accA[j]) + pairsum(pAp));      // i or f
                const float vBr = pairsum(accB[j]) + pairsum(pBp);
                const float vB = (sf == 0) ? tanh_(vBr) : sigm_(vBr);         // g or o
                const float pA = __shfl_xor_sync(0xffffffffu, vA, 16);
                const float pB = __shfl_xor_sync(0xffffffffu, vB, 16);
                const float i_ = (sf == 0) ? vA : pA;
                const float f_ = (sf == 0) ? pA : vA;
                const float g_ = (sf == 0) ? vB : pB;
                const float o_ = (sf == 0) ? pB : vB;
                c2r[j] = fmaf(f_, c2r[j], i_ * g_);
                const float h = o_ * tanh_(c2r[j]);
                if ((j & 1) == sf)
                    h2w[j * H2_STRIDE + uf] = h;
            }
        } else {
            // producer: h1 k4 12..15 + h2 k4 0..7, zero bias
            u64 accA[7], accB[7];
#pragma unroll
            for (int b = 0; b < 7; b++) { accA[b] = 0ull; accB[b] = 0ull; }
            const float* in2q = sIn2 + (qf * 7) * IN2_STRIDE;
            const float* h2q  = sH2 + ((t + 1) & 1) * H2_BUF
                                    + (qf * 7) * H2_STRIDE;        // h2(t-1)
#pragma unroll
            for (int k4 = 12; k4 < 16; k4++) {
                const ulonglong2 wa = *(const ulonglong2*)(wA + k4 * 4);
                const ulonglong2 wb = *(const ulonglong2*)(wB + k4 * 4);
#pragma unroll
                for (int b = 0; b < 7; b++) {
                    const ulonglong2 h = *(const ulonglong2*)(in2q + b * IN2_STRIDE + k4 * 4);
                    fma2(accA[b], wa.x, h.x);
                    fma2(accA[b], wa.y, h.y);
                    fma2(accB[b], wb.x, h.x);
                    fma2(accB[b], wb.y, h.y);
                }
            }
#pragma unroll 4
            for (int k4 = 0; k4 < 8; k4++) {
                const ulonglong2 wa = *(const ulonglong2*)(wA + NH1 + k4 * 4);
                const ulonglong2 wb = *(const ulonglong2*)(wB + NH1 + k4 * 4);
#pragma unroll
                for (int b = 0; b < 7; b++) {
                    const ulonglong2 h = *(const ulonglong2*)(h2q + b * H2_STRIDE + k4 * 4);
                    fma2(accA[b], wa.x, h.x);
                    fma2(accA[b], wa.y, h.y);
                    fma2(accB[b], wb.x, h.x);
                    fma2(accB[b], wb.y, h.y);
                }
            }
#pragma unroll
            for (int j = 0; j < 7; j++) {
                *(u64*)&sPart[(j * 256 + t2) * 2]       = accA[j];
                *(u64*)&sPart[((j + 7) * 256 + t2) * 2] = accB[j];
            }
            asm volatile("bar.arrive 3, 512;" ::: "memory");
        }
        // no trailing barrier: next readers are behind B,C of t+1; producers'
        // next sPart writes are behind B,C of t+1 which wait on consumers.
    }

    __syncthreads();

    // ---- final FC: out[b] = h2(T-1) . Wfc + bfc ; h2(T-1) in buf (T-1)&1 ----
    if (tid < NB) {
        const int bg = b0 + tid;
        if (bg < BATCH) {
            const float* h2f = sH2 + ((T_STEPS - 1) & 1) * H2_BUF
                                   + tid * H2_STRIDE;
            float s = bfc[0];
#pragma unroll
            for (int u = 0; u < NH2; u++)
                s = fmaf(h2f[u], sWfc[u], s);
            out[bg] = s;
        }
    }
}

extern "C" void kernel_launch(void* const* d_in, const int* in_sizes, int n_in,
                              void* d_out, int out_size)
{
    const float* x    = (const float*)d_in[0];
    const float* Wih1 = (const float*)d_in[1];
    const float* Whh1 = (const float*)d_in[2];
    const float* bih1 = (const float*)d_in[3];
    const float* bhh1 = (const float*)d_in[4];
    const float* Wih2 = (const float*)d_in[5];
    const float* Whh2 = (const float*)d_in[6];
    const float* bih2 = (const float*)d_in[7];
    const float* bhh2 = (const float*)d_in[8];
    const float* Wfc  = (const float*)d_in[9];
    const float* bfc  = (const float*)d_in[10];
    float* out = (float*)d_out;

    const size_t smem_bytes = SMEM_FLOATS * sizeof(float);  // ~217 KB
    cudaFuncSetAttribute(lstm2_fused_kernel,
                         cudaFuncAttributeMaxDynamicSharedMemorySize,
                         (int)smem_bytes);

    lstm2_fused_kernel<<<GRID, BLK, smem_bytes>>>(
        x, Wih1, Whh1, bih1, bhh1, Wih2, Whh2, bih2, bhh2, Wfc, bfc, out);
}

// round 13
// speedup vs baseline: 1.2633x; 1.0721x over previous
#include <cuda_runtime.h>

// Problem constants
#define T_STEPS 168
#define IN_DIM  16
#define NH1     64
#define NH2     32
#define NG1     256   // 4*H1
#define NG2     128   // 4*H2
#define BATCH   4096

// Tiling: one wave — 147 CTAs on 148 SMs, 512 threads each
#define NB   28
#define BLK  512
#define GRID ((BATCH + NB - 1) / NB)   // 147

// Strides (floats): ≡ 0 mod 4 (float4 align), ≡ 4 mod 8 → conflict-free
// lane-strided LDS.128
#define W1_STRIDE  84    // 16 (x) + 64 (h1) + 4 pad
#define W2_STRIDE  100   // 64 (h1) + 32 (h2) + 4 pad
#define IN1_STRIDE 84    // [0:16]=x  [16:80]=h1
#define H2_STRIDE  36    // [0:32]=h2 + 4 pad

#define IN1_BUF (NB * IN1_STRIDE)    // 2352
#define H2_BUF  (NB * H2_STRIDE)     // 1008

#define OFF_W1   0
#define OFF_W2   (OFF_W1  + NG1 * W1_STRIDE)     // 21504
#define OFF_B1   (OFF_W2  + NG2 * W2_STRIDE)     // 34304
#define OFF_B2   (OFF_B1  + NG1)                 // 34560
#define OFF_WFC  (OFF_B2  + NG2)                 // 34688
#define OFF_IN1  (OFF_WFC + 32)                  // 34720  double buffer [2][28][84]
#define OFF_H2   (OFF_IN1 + 2 * IN1_BUF)         // 39424  double buffer [2][28][36]
#define SMEM_FLOATS (OFF_H2 + 2 * H2_BUF)        // 41440 floats ≈ 166 KB

typedef unsigned long long u64;

__device__ __forceinline__ void fma2(u64& d, u64 a, u64 b) {
    asm("fma.rn.f32x2 %0, %1, %2, %0;" : "+l"(d) : "l"(a), "l"(b));
}
__device__ __forceinline__ u64 pack2(float lo, float hi) {
    u64 r; asm("mov.b64 %0, {%1, %2};" : "=l"(r) : "f"(lo), "f"(hi)); return r;
}
__device__ __forceinline__ float pairsum(u64 v) {
    float lo, hi;
    asm("mov.b64 {%0, %1}, %2;" : "=f"(lo), "=f"(hi) : "l"(v));
    return lo + hi;
}
// single-MUFU activations (MUFU.TANH)
__device__ __forceinline__ float tanh_(float v) {
    float r; asm("tanh.approx.f32 %0, %1;" : "=f"(r) : "f"(v)); return r;
}
__device__ __forceinline__ float sigm_(float v) {
    return fmaf(0.5f, tanh_(0.5f * v), 0.5f);
}

extern __shared__ float smem[];

__global__ __launch_bounds__(BLK, 1)
void lstm2_fused_kernel(const float* __restrict__ x,
                        const float* __restrict__ Wih1, const float* __restrict__ Whh1,
                        const float* __restrict__ bih1, const float* __restrict__ bhh1,
                        const float* __restrict__ Wih2, const float* __restrict__ Whh2,
                        const float* __restrict__ bih2, const float* __restrict__ bhh2,
                        const float* __restrict__ Wfc,  const float* __restrict__ bfc,
                        float* __restrict__ out)
{
    const int tid = threadIdx.x;
    const int b0  = blockIdx.x * NB;

    float* sW1  = smem + OFF_W1;
    float* sW2  = smem + OFF_W2;
    float* sB1  = smem + OFF_B1;
    float* sB2  = smem + OFF_B2;
    float* sWfc = smem + OFF_WFC;
    float* sIn1 = smem + OFF_IN1;
    float* sH2  = smem + OFF_H2;

    // ---- weights into shared (combined [x;h] rows, padded strides) ----
    for (int i = tid; i < NG1 * W1_STRIDE; i += BLK) {
        int g = i / W1_STRIDE, k = i % W1_STRIDE;
        float v = 0.f;
        if (k < IN_DIM)            v = Wih1[g * IN_DIM + k];
        else if (k < IN_DIM + NH1) v = Whh1[g * NH1 + (k - IN_DIM)];
        sW1[i] = v;
    }
    for (int i = tid; i < NG2 * W2_STRIDE; i += BLK) {
        int g = i / W2_STRIDE, k = i % W2_STRIDE;
        float v = 0.f;
        if (k < NH1)            v = Wih2[g * NH1 + k];
        else if (k < NH1 + NH2) v = Whh2[g * NH2 + (k - NH1)];
        sW2[i] = v;
    }
    if (tid < NG1) sB1[tid] = bih1[tid] + bhh1[tid];
    if (tid < NG2) sB2[tid] = bih2[tid] + bhh2[tid];
    if (tid < NH2) sWfc[tid] = Wfc[tid];
    for (int i = tid; i < 2 * IN1_BUF; i += BLK) sIn1[i] = 0.f;
    for (int i = tid; i < 2 * H2_BUF;  i += BLK) sH2[i] = 0.f;

    // ---- L1 mapping (tid 0..255): thread = (unit u1, quarter q), 4 gates x 7 b
    const int u1 = tid & 63;
    const int q  = tid >> 6;                     // 0..3 (uniform per 2 warps)
    const float* w1i = sW1 + u1 * W1_STRIDE;
    const float* w1f = sW1 + (64 + u1) * W1_STRIDE;
    const float* w1g = sW1 + (128 + u1) * W1_STRIDE;
    const float* w1o = sW1 + (192 + u1) * W1_STRIDE;

    // ---- L2 mapping (tid 256..511): R8-style fused45, G=2 + xor-16 shfl
    const int t2 = tid & 255;
    const int uf = ((t2 >> 5) & 1) * 16 + (t2 & 15);   // 0..31
    const int sf = (t2 >> 4) & 1;
    const int qf = t2 >> 6;                            // 0..3
    const float* wA = sW2 + (uf + sf * 32) * W2_STRIDE;        // i or f
    const float* wB = sW2 + (uf + 64 + sf * 32) * W2_STRIDE;   // g or o

    // ---- x publishers: threads 256..367 (112), one float4 (b, k4) each ----
    const int  xi   = tid - 256;
    const bool xact = (tid >= 256) && (xi < NB * (IN_DIM / 4));  // 112
    const int  xb   = xi >> 2;
    const int  xk4  = xi & 3;
    const bool xval = xact && (b0 + xb) < BATCH;
    const float* xptr = xval ? (x + ((long)(b0 + xb) * T_STEPS) * IN_DIM + xk4 * 4)
                             : x;
    float4 xreg = make_float4(0.f, 0.f, 0.f, 0.f);
    if (xval) xreg = *(const float4*)xptr;

    __syncthreads();
    if (xact) *(float4*)&sIn1[xb * IN1_STRIDE + xk4 * 4] = xreg;   // x(0) -> buf0
    if (xval) xreg = *(const float4*)(xptr + IN_DIM);              // x(1)
    __syncthreads();

    // ---- bias reads — after barrier so init writes are visible ----
    const float bi1 = sB1[u1];
    const float bf1 = sB1[64 + u1];
    const float bg1 = sB1[128 + u1];
    const float bo1 = sB1[192 + u1];
    const float bbA = sB2[uf + sf * 32];
    const float bbB = sB2[uf + 64 + sf * 32];

    float c1r[7], c2r[7];
#pragma unroll
    for (int j = 0; j < 7; j++) { c1r[j] = 0.f; c2r[j] = 0.f; }

    for (int t = 0; t <= T_STEPS; t++) {
        const float* rb = sIn1 + (t & 1) * IN1_BUF;        // x(t), h1(t-1)
        float*       wb = sIn1 + ((t + 1) & 1) * IN1_BUF;  // x(t+1), h1(t)

        if (tid < 256) {
            // ---- L1: all 4 gates of unit u1, 7 batches; cell update local ----
            if (t < T_STEPS) {
                u64 ai[7], af[7], ag[7], ao[7];
#pragma unroll
                for (int b = 0; b < 7; b++) {
                    ai[b] = pack2(bi1, 0.f);
                    af[b] = pack2(bf1, 0.f);
                    ag[b] = pack2(bg1, 0.f);
                    ao[b] = pack2(bo1, 0.f);
                }
                const float* in1q = rb + (q * 7) * IN1_STRIDE;
#pragma unroll 4
                for (int k4 = 0; k4 < (IN_DIM + NH1) / 4; k4++) {      // 20
                    const ulonglong2 wi = *(const ulonglong2*)(w1i + k4 * 4);
                    const ulonglong2 wf = *(const ulonglong2*)(w1f + k4 * 4);
                    const ulonglong2 wg = *(const ulonglong2*)(w1g + k4 * 4);
                    const ulonglong2 wo = *(const ulonglong2*)(w1o + k4 * 4);
#pragma unroll
                    for (int b = 0; b < 7; b++) {
                        const ulonglong2 h =
                            *(const ulonglong2*)(in1q + b * IN1_STRIDE + k4 * 4);
                        fma2(ai[b], wi.x, h.x); fma2(ai[b], wi.y, h.y);
                        fma2(af[b], wf.x, h.x); fma2(af[b], wf.y, h.y);
                        fma2(ag[b], wg.x, h.x); fma2(ag[b], wg.y, h.y);
                        fma2(ao[b], wo.x, h.x); fma2(ao[b], wo.y, h.y);
                    }
                }
                // epilogue: all gates local — update c1, write h1(t)
#pragma unroll
                for (int j = 0; j < 7; j++) {
                    const float i_ = sigm_(pairsum(ai[j]));
                    const float f_ = sigm_(pairsum(af[j]));
                    const float g_ = tanh_(pairsum(ag[j]));
                    const float o_ = sigm_(pairsum(ao[j]));
                    c1r[j] = fmaf(f_, c1r[j], i_ * g_);
                    wb[(q * 7 + j) * IN1_STRIDE + IN_DIM + u1] = o_ * tanh_(c1r[j]);
                }
            }
        } else {
            // ---- publish x(t+1) into write buffer; prefetch x(t+2) ----
            if (t < T_STEPS) {
                if (xact && (t + 1) < T_STEPS)
                    *(float4*)&wb[xb * IN1_STRIDE + xk4 * 4] = xreg;
                if (xval && (t + 2) < T_STEPS)
                    xreg = *(const float4*)(xptr + (long)(t + 2) * IN_DIM);
            }
            // ---- L2 fused: gates(t-1) + cell(t-1) ----
            if (t >= 1) {
                u64 accA[7], accB[7];
#pragma unroll
                for (int b = 0; b < 7; b++) {
                    accA[b] = pack2(bbA, 0.f);
                    accB[b] = pack2(bbB, 0.f);
                }
                const float* h1q = rb + (qf * 7) * IN1_STRIDE + IN_DIM;       // h1(t-1)
                const float* h2q = sH2 + (t & 1) * H2_BUF + (qf * 7) * H2_STRIDE; // h2(t-2)
#pragma unroll 4
                for (int k4 = 0; k4 < NH1 / 4; k4++) {                  // 16
                    const ulonglong2 wa = *(const ulonglong2*)(wA + k4 * 4);
                    const ulonglong2 wbv = *(const ulonglong2*)(wB + k4 * 4);
#pragma unroll
                    for (int b = 0; b < 7; b++) {
                        const ulonglong2 h =
                            *(const ulonglong2*)(h1q + b * IN1_STRIDE + k4 * 4);
                        fma2(accA[b], wa.x, h.x);
                        fma2(accA[b], wa.y, h.y);
                        fma2(accB[b], wbv.x, h.x);
                        fma2(accB[b], wbv.y, h.y);
                    }
                }
#pragma unroll 4
                for (int k4 = 0; k4 < NH2 / 4; k4++) {                  // 8
                    const ulonglong2 wa = *(const ulonglong2*)(wA + NH1 + k4 * 4);
                    const ulonglong2 wbv = *(const ulonglong2*)(wB + NH1 + k4 * 4);
#pragma unroll
                    for (int b = 0; b < 7; b++) {
                        const ulonglong2 h =
                            *(const ulonglong2*)(h2q + b * H2_STRIDE + k4 * 4);
                        fma2(accA[b], wa.x, h.x);
                        fma2(accA[b], wa.y, h.y);
                        fma2(accB[b], wbv.x, h.x);
                        fma2(accB[b], wbv.y, h.y);
                    }
                }
                float* h2w = sH2 + ((t + 1) & 1) * H2_BUF + (qf * 7) * H2_STRIDE; // h2(t-1)
#pragma unroll
                for (int j = 0; j < 7; j++) {
                    const float vA = sigm_(pairsum(accA[j]));             // i or f
                    const float vBr = pairsum(accB[j]);
                    const float vB = (sf == 0) ? tanh_(vBr) : sigm_(vBr); // g or o
                    const float pA = __shfl_xor_sync(0xffffffffu, vA, 16);
                    const float pB = __shfl_xor_sync(0xffffffffu, vB, 16);
                    const float i_ = (sf == 0) ? vA : pA;
                    const float f_ = (sf == 0) ? pA : vA;
                    const float g_ = (sf == 0) ? vB : pB;
                    const float o_ = (sf == 0) ? pB : vB;
                    c2r[j] = fmaf(f_, c2r[j], i_ * g_);
                    const float h = o_ * tanh_(c2r[j]);
                    if ((j & 1) == sf)
                        h2w[j * H2_STRIDE + uf] = h;
                }
            }
        }

        __syncthreads();                 // single per-step barrier
    }

    // ---- final FC: out[b] = h2(T-1) . Wfc + bfc ----
    // h2(T-1) written at iteration t=T into buffer ((T+1)&1)
    if (tid < NB) {
        const int bg = b0 + tid;
        if (bg < BATCH) {
            const float* h2f = sH2 + ((T_STEPS + 1) & 1) * H2_BUF
                                   + tid * H2_STRIDE;
            float s = bfc[0];
#pragma unroll
            for (int u = 0; u < NH2; u++)
                s = fmaf(h2f[u], sWfc[u], s);
            out[bg] = s;
        }
    }
}

extern "C" void kernel_launch(void* const* d_in, const int* in_sizes, int n_in,
                              void* d_out, int out_size)
{
    const float* x    = (const float*)d_in[0];
    const float* Wih1 = (const float*)d_in[1];
    const float* Whh1 = (const float*)d_in[2];
    const float* bih1 = (const float*)d_in[3];
    const float* bhh1 = (const float*)d_in[4];
    const float* Wih2 = (const float*)d_in[5];
    const float* Whh2 = (const float*)d_in[6];
    const float* bih2 = (const float*)d_in[7];
    const float* bhh2 = (const float*)d_in[8];
    const float* Wfc  = (const float*)d_in[9];
    const float* bfc  = (const float*)d_in[10];
    float* out = (float*)d_out;

    const size_t smem_bytes = SMEM_FLOATS * sizeof(float);  // ~166 KB
    cudaFuncSetAttribute(lstm2_fused_kernel,
                         cudaFuncAttributeMaxDynamicSharedMemorySize,
                         (int)smem_bytes);

    lstm2_fused_kernel<<<GRID, BLK, smem_bytes>>>(
        x, Wih1, Whh1, bih1, bhh1, Wih2, Whh2, bih2, bhh2, Wfc, bfc, out);
}